// round 15
// baseline (speedup 1.0000x reference)
#include <cuda_runtime.h>
#include <cuda_bf16.h>
#include <cuda_fp16.h>
#include <math.h>

#define B 2
#define C 64
#define C4 16
#define H 128
#define Wd 128
#define HW (H * Wd)
#define EPSF 1e-6f

typedef unsigned long long u64;
typedef unsigned int u32;

// ---------------- scratch (device globals; no allocation allowed) ----------------
__device__ __align__(16) u32 g_gb[B * C * HW];               // (bf16 gx, bf16 gy) per px
__device__ float g_cons[B * HW];
__device__ float g_ew[B * HW];
__device__ __align__(16) __nv_bfloat16 g_ga2b[B * HW * C4];  // ga2, px-major bf16
__device__ __align__(16) __half g_xb[B * HW * C];            // x, NHWC fp16
__device__ __align__(16) __half g_eeb[B * HW * C];           // relu(conv1), NHWC fp16
__device__ __align__(16) u64 g_wq[2 * 9 * 4 * 64 * 4];       // conv B frags fp16 [tap][kc][pr][lane][2]
__device__ __align__(16) u64 g_wga1[2048];                   // ga layer1 B fragments (bf16)
__device__ __align__(16) u64 g_wga2[256];                    // ga layer2 B fragments (bf16)
__device__ __align__(16) u64 g_wcd[576];                     // cd conv B fragments (bf16)

__device__ __forceinline__ u32 s2u(const void* p) {
    return (u32)__cvta_generic_to_shared(p);
}

// ---------------- fast math ----------------
__device__ __forceinline__ float fsqrt_ap(float v) {
    float r; asm("sqrt.approx.f32 %0, %1;" : "=f"(r) : "f"(v)); return r;
}
__device__ __forceinline__ float ftanh_ap(float v) {
    float r; asm("tanh.approx.f32 %0, %1;" : "=f"(r) : "f"(v)); return r;
}
__device__ __forceinline__ float frcp_ap(float v) {
    float r; asm("rcp.approx.f32 %0, %1;" : "=f"(r) : "f"(v)); return r;
}
__device__ __forceinline__ float fatan2_ap(float y, float x) {
    float ax = fabsf(x), ay = fabsf(y);
    float mx = fmaxf(ax, ay), mn = fminf(ax, ay);
    float z = __fdividef(mn, fmaxf(mx, 1e-30f));
    float s = z * z;
    float p = fmaf(s, -0.0117212f, 0.0526533f);
    p = fmaf(s, p, -0.1164329f);
    p = fmaf(s, p, 0.1935435f);
    p = fmaf(s, p, -0.3326235f);
    p = fmaf(s, p, 0.9999773f);
    float r = p * z;
    if (ay > ax) r = 1.57079632679f - r;
    if (x < 0.f) r = 3.14159265359f - r;
    return copysignf(r, y);
}

// ---------------- K_PRE: weight packs + g_cons zero + x->NHWC fp16 + sobel ----
__global__ __launch_bounds__(256) void k_pre(const float* __restrict__ x,
                                             const float* __restrict__ w1,
                                             const float* __restrict__ w2,
                                             const float* __restrict__ gw1,
                                             const float* __restrict__ gw2,
                                             const float* __restrict__ cw1) {
    __shared__ __align__(16) char sm[16640];
    int bx = blockIdx.x, tid = threadIdx.x;

    if (bx < 128) {
        int i = bx * 256 + tid;
        g_cons[i] = 0.f;
        if (i < 2 * 9216) {      // ec conv weights (fp16): [tap][kc][pr][lane][half]
            int cv = i / 9216;
            int r = i % 9216;
            int dlt = r / 1024;
            int r2 = r % 1024;
            int kc = r2 / 256;
            int rr = r2 % 256;
            int pr = rr >> 6;
            int rr2 = rr & 63;
            int nq = rr2 >> 1;
            int half = rr2 & 1;
            int nt = pr * 2 + half;
            int n = nt * 8 + (nq >> 2);
            int q = nq & 3;
            const float* w = cv ? w2 : w1;
            int ic0 = kc * 16 + 2 * q;
            __half2 lo = __floats2half2_rn(
                w[(n * 64 + ic0) * 9 + dlt], w[(n * 64 + ic0 + 1) * 9 + dlt]);
            __half2 hi = __floats2half2_rn(
                w[(n * 64 + ic0 + 8) * 9 + dlt], w[(n * 64 + ic0 + 9) * 9 + dlt]);
            g_wq[i] = (u64)(*(u32*)&lo) | ((u64)(*(u32*)&hi) << 32);
        }
        if (i < 2048) {          // ga_w1 fragments, interleaved k (bf16)
            int kstep = i >> 8;
            int nt = (i >> 5) & 7;
            int l = i & 31;
            int n_oc = nt * 8 + (l >> 2);
            int kn0 = kstep * 16 + (l & 3) * 2;
            int ch = kn0 >> 1;
            __nv_bfloat162 lo = __floats2bfloat162_rn(
                gw1[n_oc * 128 + ch], gw1[n_oc * 128 + 64 + ch]);
            __nv_bfloat162 hi = __floats2bfloat162_rn(
                gw1[n_oc * 128 + ch + 4], gw1[n_oc * 128 + 64 + ch + 4]);
            g_wga1[i] = (u64)(*(u32*)&lo) | ((u64)(*(u32*)&hi) << 32);
        }
        if (i < 256) {           // ga_w2 fragments (bf16)
            int kstep = i >> 6;
            int nt = (i >> 5) & 1;
            int l = i & 31;
            int n_oc = nt * 8 + (l >> 2);
            int k0 = kstep * 16 + (l & 3) * 2;
            __nv_bfloat162 lo = __floats2bfloat162_rn(
                gw2[n_oc * 64 + k0], gw2[n_oc * 64 + k0 + 1]);
            __nv_bfloat162 hi = __floats2bfloat162_rn(
                gw2[n_oc * 64 + k0 + 8], gw2[n_oc * 64 + k0 + 9]);
            g_wga2[i] = (u64)(*(u32*)&lo) | ((u64)(*(u32*)&hi) << 32);
        }
        if (i < 576) {           // cd conv fragments (bf16)
            int tap = i >> 6;
            int nt = (i >> 5) & 1;
            int l = i & 31;
            int n_oc = nt * 8 + (l >> 2);
            int ic0 = (l & 3) * 2;
            __nv_bfloat162 lo = __floats2bfloat162_rn(
                cw1[(n_oc * 16 + ic0) * 9 + tap],
                cw1[(n_oc * 16 + ic0 + 1) * 9 + tap]);
            __nv_bfloat162 hi = __floats2bfloat162_rn(
                cw1[(n_oc * 16 + ic0 + 8) * 9 + tap],
                cw1[(n_oc * 16 + ic0 + 9) * 9 + tap]);
            g_wcd[i] = (u64)(*(u32*)&lo) | ((u64)(*(u32*)&hi) << 32);
        }
    } else if (bx < 640) {
        int bb = bx - 128;
        int b = bb >> 8;
        int px0 = (bb & 255) * 64;
        float* s = (float*)sm;
        const float* xb = x + (size_t)b * C * HW;
        for (int i = tid; i < 4096; i += 256) {
            int ic = i >> 6, p = i & 63;
            s[p * 65 + ic] = xb[(size_t)ic * HW + px0 + p];
        }
        __syncthreads();
#pragma unroll
        for (int it = 0; it < 2; it++) {
            int idx = tid + it * 256;
            int p = idx >> 3, seg = idx & 7;
            const float* sp = &s[p * 65 + seg * 8];
            u32 u[4];
#pragma unroll
            for (int k = 0; k < 4; k++) {
                __half2 h2 = __floats2half2_rn(sp[2 * k], sp[2 * k + 1]);
                u[k] = *(u32*)&h2;
            }
            *(uint4*)&g_xb[((size_t)b * HW + px0 + p) * 64 + seg * 8] =
                make_uint4(u[0], u[1], u[2], u[3]);
        }
    } else {
        int z = bx - 640;
        int plane = z >> 4;
        int oy = ((z >> 2) & 3) * 32, ox = (z & 3) * 32;
        float* sx = (float*)sm;
        const float* xp = x + (size_t)plane * HW;
        for (int i = tid; i < 1156; i += 256) {
            int r = i / 34, c = i - r * 34;
            int gh = oy + r - 1, gw = ox + c - 1;
            float v = 0.f;
            if ((unsigned)gh < (unsigned)H && (unsigned)gw < (unsigned)Wd)
                v = xp[gh * Wd + gw];
            sx[r * 34 + c] = v;
        }
        __syncthreads();
#pragma unroll
        for (int k = 0; k < 4; k++) {
            int px = tid + k * 256;
            int row = px >> 5, col = px & 31;
            const float* s0 = sx + row * 34 + col;
            float a00 = s0[0],  a01 = s0[1],  a02 = s0[2];
            float a10 = s0[34],               a12 = s0[36];
            float a20 = s0[68], a21 = s0[69], a22 = s0[70];
            float gx = (a02 - a00) + 2.f * (a12 - a10) + (a22 - a20);
            float gy = (a20 - a00) + 2.f * (a21 - a01) + (a22 - a02);
            __nv_bfloat162 hv = __floats2bfloat162_rn(gx, gy);
            g_gb[plane * HW + (oy + row) * Wd + ox + col] = *(u32*)&hv;
        }
    }
}

// ---------------- K23: merged k3 (consistency) + k2 (1x1 mma chain) -----------
#define K23_SMEM 43328
extern "C" __global__ void __launch_bounds__(128)
k23(const float* __restrict__ b1, const float* __restrict__ b2) {
    extern __shared__ char dsm[];
    int tid = threadIdx.x;
    int bi = blockIdx.x;

    if (bi < 2048) {
        int b = bi >> 10;
        int rem = bi & 1023;
        int c = rem >> 4;
        int tile = rem & 15;
        int oy = (tile >> 2) * 32, ox = (tile & 3) * 32;
        float* sm0 = (float*)dsm;
        float* sm1 = sm0 + 1296;
        float* sm2 = sm1 + 1296;
        float* h0 = sm2 + 1296;
        float* h1 = h0 + 1152;
        float* h2 = h1 + 1152;

        const u32* gb = g_gb + (size_t)(b * C + c) * HW;
        for (int i = tid; i < 1296; i += 128) {
            int r = i / 36, k = i - r * 36;
            int gh = oy + r - 2, gw = ox + k - 2;
            float m0 = 0.f, m1 = 0.f, m2 = 0.f;
            if ((unsigned)gh < (unsigned)H && (unsigned)gw < (unsigned)Wd) {
                u32 v = gb[gh * Wd + gw];
                float2 g = __bfloat1622float2(*(__nv_bfloat162*)&v);
                float gx = g.x, gy = g.y;
                float mag = fsqrt_ap(gx * gx + gy * gy + EPSF);
                float dir = fatan2_ap(gy, gx);
                m0 = mag;
                m1 = mag * dir;
                m2 = m1 * dir;
            }
            sm0[i] = m0;
            sm1[i] = m1;
            sm2[i] = m2;
        }
        __syncthreads();
        for (int i = tid; i < 1152; i += 128) {
            int r = i >> 5, k = i & 31;
            const float* p0 = sm0 + r * 36 + k;
            const float* p1 = sm1 + r * 36 + k;
            const float* p2 = sm2 + r * 36 + k;
            float a0 = 0.f, a1 = 0.f, a2 = 0.f;
#pragma unroll
            for (int d = 0; d < 5; d++) {
                a0 += p0[d];
                a1 += p1[d];
                a2 += p2[d];
            }
            h0[i] = a0;
            h1[i] = a1;
            h2[i] = a2;
        }
        __syncthreads();
        int ty = tid >> 5, tx = tid & 31;
#pragma unroll
        for (int j = 0; j < 8; j++) {
            int row = j * 4 + ty;
            float s0 = 0.f, s1 = 0.f, s2 = 0.f;
#pragma unroll
            for (int d = 0; d < 5; d++) {
                s0 += h0[(row + d) * 32 + tx];
                s1 += h1[(row + d) * 32 + tx];
                s2 += h2[(row + d) * 32 + tx];
            }
            float inv = frcp_ap(s0 + EPSF);
            float wmean = s1 * inv;
            float wvar = (s2 - 2.f * wmean * s1 + wmean * wmean * s0) * inv;
            wvar = fmaxf(wvar, 0.f);
            float cv = (1.f - ftanh_ap(fsqrt_ap(wvar))) * (1.f / (float)C);
            atomicAdd(&g_cons[b * HW + (oy + row) * Wd + (ox + tx)], cv);
        }
        return;
    }

    __nv_bfloat16* sIn = (__nv_bfloat16*)dsm;
    __nv_bfloat16* sHid = (__nv_bfloat16*)(dsm + 16384);
    u64* sW1 = (u64*)(dsm + 24576);
    u64* sW2 = (u64*)(dsm + 40960);
    float* sb1 = (float*)(dsm + 43008);
    float* sb2 = (float*)(dsm + 43264);

    int lane = tid & 31, w = tid >> 5;
    int bk = bi - 2048;
    int b = bk >> 8;
    int px0 = (bk & 255) * 64;

    {
        const float4* s1 = (const float4*)g_wga1;
        float4* d1 = (float4*)sW1;
#pragma unroll
        for (int i = tid; i < 1024; i += 128) d1[i] = s1[i];
        ((float4*)sW2)[tid] = ((const float4*)g_wga2)[tid];
        if (tid < 64) sb1[tid] = b1[tid];
        if (tid < 16) sb2[tid] = b2[tid];
    }
    const u32* gbb = g_gb + (size_t)b * C * HW + px0;
    for (int i = tid; i < 4096; i += 128) {
        int cp = i >> 6, px = i & 63;
        u32 v = gbb[(size_t)cp * HW + px];
        int half = cp >> 5, c4 = (cp & 31) * 4;
        *(u32*)(dsm + half * 8192 + px * 128 +
                ((u32)c4 ^ ((u32)(px & 7) << 4))) = v;
    }
    __syncthreads();

    int m = lane & 15, kb = (lane >> 4) << 4;
    int p = w * 16 + m;
    u32 swz = (u32)((p & 7) << 4);
    u32 arow = s2u(sIn) + p * 128;

    float acc[8][4];
#pragma unroll
    for (int nt = 0; nt < 8; nt++)
#pragma unroll
        for (int k = 0; k < 4; k++) acc[nt][k] = 0.f;

#pragma unroll
    for (int kc = 0; kc < 8; kc++) {
        u32 a0, a1, a2, a3;
        u32 addr = arow + (kc >> 2) * 8192 + (((u32)((kc & 3) * 32 + kb)) ^ swz);
        asm volatile(
            "ldmatrix.sync.aligned.m8n8.x4.shared.b16 {%0,%1,%2,%3}, [%4];"
            : "=r"(a0), "=r"(a1), "=r"(a2), "=r"(a3) : "r"(addr));
        const u64* wk = sW1 + (size_t)kc * 256 + lane;
#pragma unroll
        for (int nt = 0; nt < 8; nt++) {
            u64 bv = wk[nt * 32];
            u32 bf0 = (u32)bv, bf1 = (u32)(bv >> 32);
            asm volatile(
                "mma.sync.aligned.m16n8k16.row.col.f32.bf16.bf16.f32 "
                "{%0,%1,%2,%3}, {%4,%5,%6,%7}, {%8,%9}, {%0,%1,%2,%3};"
                : "+f"(acc[nt][0]), "+f"(acc[nt][1]),
                  "+f"(acc[nt][2]), "+f"(acc[nt][3])
                : "r"(a0), "r"(a1), "r"(a2), "r"(a3), "r"(bf0), "r"(bf1));
        }
    }

    int rr = lane >> 2, cc0 = (lane & 3) * 2;
    int pr0 = w * 16 + rr, pr1 = pr0 + 8;
#pragma unroll
    for (int nt = 0; nt < 8; nt++) {
        int oc = nt * 8 + cc0;
        float bb0 = sb1[oc], bb1 = sb1[oc + 1];
        __nv_bfloat162 v01 = __floats2bfloat162_rn(
            fmaxf(acc[nt][0] + bb0, 0.f), fmaxf(acc[nt][1] + bb1, 0.f));
        __nv_bfloat162 v23 = __floats2bfloat162_rn(
            fmaxf(acc[nt][2] + bb0, 0.f), fmaxf(acc[nt][3] + bb1, 0.f));
        *(u32*)((char*)sHid + pr0 * 128 +
                ((u32)(oc * 2) ^ ((u32)(pr0 & 7) << 4))) = *(u32*)&v01;
        *(u32*)((char*)sHid + pr1 * 128 +
                ((u32)(oc * 2) ^ ((u32)(pr1 & 7) << 4))) = *(u32*)&v23;
    }
    __syncwarp();

    float a2c[2][4];
#pragma unroll
    for (int nt = 0; nt < 2; nt++)
#pragma unroll
        for (int k = 0; k < 4; k++) a2c[nt][k] = 0.f;

    u32 hrow = s2u(sHid) + p * 128;
#pragma unroll
    for (int kc = 0; kc < 4; kc++) {
        u32 a0, a1, a2, a3;
        u32 addr = hrow + (((u32)(kc * 32 + kb)) ^ swz);
        asm volatile(
            "ldmatrix.sync.aligned.m8n8.x4.shared.b16 {%0,%1,%2,%3}, [%4];"
            : "=r"(a0), "=r"(a1), "=r"(a2), "=r"(a3) : "r"(addr));
        const u64* wk = sW2 + (size_t)kc * 64 + lane;
#pragma unroll
        for (int nt = 0; nt < 2; nt++) {
            u64 bv = wk[nt * 32];
            u32 bf0 = (u32)bv, bf1 = (u32)(bv >> 32);
            asm volatile(
                "mma.sync.aligned.m16n8k16.row.col.f32.bf16.bf16.f32 "
                "{%0,%1,%2,%3}, {%4,%5,%6,%7}, {%8,%9}, {%0,%1,%2,%3};"
                : "+f"(a2c[nt][0]), "+f"(a2c[nt][1]),
                  "+f"(a2c[nt][2]), "+f"(a2c[nt][3])
                : "r"(a0), "r"(a1), "r"(a2), "r"(a3), "r"(bf0), "r"(bf1));
        }
    }

    size_t pxg0 = (size_t)b * HW + px0 + w * 16 + rr;
#pragma unroll
    for (int nt = 0; nt < 2; nt++) {
        int oc = nt * 8 + cc0;
        float bb0 = sb2[oc], bb1 = sb2[oc + 1];
        __nv_bfloat162 v01 = __floats2bfloat162_rn(
            fmaxf(a2c[nt][0] + bb0, 0.f), fmaxf(a2c[nt][1] + bb1, 0.f));
        __nv_bfloat162 v23 = __floats2bfloat162_rn(
            fmaxf(a2c[nt][2] + bb0, 0.f), fmaxf(a2c[nt][3] + bb1, 0.f));
        *(u32*)&g_ga2b[pxg0 * 16 + oc] = *(u32*)&v01;
        *(u32*)&g_ga2b[(pxg0 + 8) * 16 + oc] = *(u32*)&v23;
    }
}

// ---------------- conv config: 512 threads (16 warps), shared Xs + weights -----
#define XS_BYTES 23040
#define WS_BYTES 73728
#define CONV_SMEM (XS_BYTES + WS_BYTES)

// stage Xs (group0, with ky0 weights) + ky1 (group1) + ky2 (group2); 512 threads
__device__ __forceinline__ void conv_stage_async(u32 xs_s, u32 ws_s,
                                                 const __half* xb,
                                                 const char* wsrc,
                                                 int brow, int bcol, int tid) {
    for (int i = tid; i < 1440; i += 512) {
        int p = i >> 3, seg = i & 7;
        int r = p / 18, c = p - r * 18;
        int gh = brow - 1 + r, gc = bcol - 1 + c;
        bool ok = (unsigned)gh < (unsigned)H && (unsigned)gc < (unsigned)Wd;
        const char* src = (const char*)xb +
                          (ok ? ((size_t)(gh * Wd + gc)) * 128 + seg * 16 : 0);
        int sz = ok ? 16 : 0;
        u32 dst = xs_s + (u32)(p * 128 + ((seg * 16) ^ ((p & 7) << 4)));
        asm volatile("cp.async.ca.shared.global [%0], [%1], 16, %2;"
                     :: "r"(dst), "l"(src), "r"(sz) : "memory");
    }
#pragma unroll
    for (int j = 0; j < 3; j++) {
        int i = j * 512 + tid;
        asm volatile("cp.async.ca.shared.global [%0], [%1], 16;"
                     :: "r"(ws_s + i * 16), "l"(wsrc + (size_t)i * 16) : "memory");
    }
    asm volatile("cp.async.commit_group;" ::: "memory");
#pragma unroll
    for (int g3 = 1; g3 < 3; g3++) {
#pragma unroll
        for (int j = 0; j < 3; j++) {
            int i = g3 * 1536 + j * 512 + tid;
            asm volatile("cp.async.ca.shared.global [%0], [%1], 16;"
                         :: "r"(ws_s + i * 16), "l"(wsrc + (size_t)i * 16)
                         : "memory");
        }
        asm volatile("cp.async.commit_group;" ::: "memory");
    }
}

// core fp16 mma: warp w -> row (w&7), oc-group (w>>3). acc[4][2] half2-pairs.
__device__ __forceinline__ void conv_mma_core(u32 acc[4][2], u32 xs_base,
                                              const u64* Ws, int lane, int w) {
    int row = w & 7, ocg = w >> 3;
    int m = lane & 15;
    int kb = (lane >> 4) << 4;
#pragma unroll
    for (int ky = 0; ky < 3; ky++) {
        if (ky == 0) asm volatile("cp.async.wait_group 2;" ::: "memory");
        else if (ky == 1) asm volatile("cp.async.wait_group 1;" ::: "memory");
        else asm volatile("cp.async.wait_group 0;" ::: "memory");
        __syncthreads();
#pragma unroll
        for (int kx = 0; kx < 3; kx++) {
            int p = (row + ky) * 18 + kx + m;
            u32 arow = xs_base + p * 128;
            u32 swz = (u32)((p & 7) << 4);
            const u64* wtap = Ws + (ky * 3 + kx) * 1024 + ocg * 128 + lane * 2;
#pragma unroll
            for (int kc = 0; kc < 4; kc++) {
                u32 a0, a1, a2, a3;
                u32 addr = arow + ((u32)(kc * 32 + kb) ^ swz);
                asm volatile(
                    "ldmatrix.sync.aligned.m8n8.x4.shared.b16 "
                    "{%0,%1,%2,%3}, [%4];"
                    : "=r"(a0), "=r"(a1), "=r"(a2), "=r"(a3)
                    : "r"(addr));
                const u64* wk = wtap + kc * 256;
#pragma unroll
                for (int prl = 0; prl < 2; prl++) {
                    ulonglong2 bv2 = *(const ulonglong2*)(wk + prl * 64);
                    u32 b0 = (u32)bv2.x, b1 = (u32)(bv2.x >> 32);
                    asm volatile(
                        "mma.sync.aligned.m16n8k16.row.col.f16.f16.f16.f16 "
                        "{%0,%1}, {%2,%3,%4,%5}, {%6,%7}, {%0,%1};"
                        : "+r"(acc[2 * prl][0]), "+r"(acc[2 * prl][1])
                        : "r"(a0), "r"(a1), "r"(a2), "r"(a3),
                          "r"(b0), "r"(b1));
                    u32 b2 = (u32)bv2.y, b3 = (u32)(bv2.y >> 32);
                    asm volatile(
                        "mma.sync.aligned.m16n8k16.row.col.f16.f16.f16.f16 "
                        "{%0,%1}, {%2,%3,%4,%5}, {%6,%7}, {%0,%1};"
                        : "+r"(acc[2 * prl + 1][0]), "+r"(acc[2 * prl + 1][1])
                        : "r"(a0), "r"(a1), "r"(a2), "r"(a3),
                          "r"(b2), "r"(b3));
                }
            }
        }
    }
}

// ---------------- KMID: merged conv1 (512 thr) + k4 (512 thr, 16-row tiles) ----
extern "C" __global__ void __launch_bounds__(512, 2)
kmid(const float* __restrict__ ecb1,
     const float* __restrict__ cb1, const float* __restrict__ cw2,
     const float* __restrict__ cb2) {
    extern __shared__ char dsm[];
    __shared__ u32 sbias2[32];
    int tid = threadIdx.x;
    int lane = tid & 31, w = tid >> 5;
    int bi = blockIdx.x;

    if (bi < 256) {
        __half* Xs = (__half*)dsm;
        u64* Ws = (u64*)(dsm + XS_BYTES);
        int b = bi >> 7;
        int rem = bi & 127;
        int brow = (rem >> 3) * 8, bcol = (rem & 7) * 16;

        conv_stage_async(s2u(Xs), s2u(Ws),
                         g_xb + (size_t)b * HW * 64, (const char*)g_wq,
                         brow, bcol, tid);
        if (tid < 32) {
            __half2 bp = __floats2half2_rn(ecb1[2 * tid], ecb1[2 * tid + 1]);
            sbias2[tid] = *(u32*)&bp;
        }

        u32 acc[4][2];
#pragma unroll
        for (int nt = 0; nt < 4; nt++) { acc[nt][0] = 0u; acc[nt][1] = 0u; }

        conv_mma_core(acc, s2u(Xs), Ws, lane, w);

        int row = w & 7, ocg = w >> 3;
        int g = lane >> 2, t = lane & 3;
        int h = brow + row;
        size_t px0 = (size_t)b * HW + h * Wd + bcol + g;
        __half2 zero2 = __floats2half2_rn(0.f, 0.f);
#pragma unroll
        for (int nt = 0; nt < 4; nt++) {
            int oc = ocg * 32 + nt * 8 + 2 * t;
            __half2 bp = *(__half2*)&sbias2[oc >> 1];
            __half2 v0 = __hmax2(__hadd2(*(__half2*)&acc[nt][0], bp), zero2);
            __half2 v1 = __hmax2(__hadd2(*(__half2*)&acc[nt][1], bp), zero2);
            *(u32*)&g_eeb[px0 * 64 + oc] = *(u32*)&v0;
            *(u32*)&g_eeb[(px0 + 8) * 64 + oc] = *(u32*)&v1;
        }
        return;
    }

    // ---- k4: cd branch, 16 warps -> 16 px rows per block ----
    char* sga = dsm;                          // 324 px * 48B = 15552
    u64* sW = (u64*)(dsm + 15552);            // 576 u64
    __shared__ float b1s[16], w2s[16];
    __shared__ float b2s_;

    int bk = bi - 256;                        // [0,128)
    int b = bk >> 6;
    int t6 = bk & 63;
    int brow = (t6 >> 3) * 16, bcol = (t6 & 7) * 16;

    for (int i = tid; i < 576; i += 512) sW[i] = g_wcd[i];
    if (tid < 16) { b1s[tid] = cb1[tid]; w2s[tid] = cw2[tid]; }
    if (tid == 0) b2s_ = cb2[0];

    const __nv_bfloat16* gb = g_ga2b + (size_t)b * HW * 16;
    for (int i = tid; i < 648; i += 512) {
        int p = i >> 1, hf = i & 1;
        int r = p / 18, c = p - r * 18;
        int gh = brow - 1 + r, gc = bcol - 1 + c;
        uint4 v = make_uint4(0, 0, 0, 0);
        if ((unsigned)gh < (unsigned)H && (unsigned)gc < (unsigned)Wd)
            v = *(const uint4*)&gb[(size_t)(gh * Wd + gc) * 16 + hf * 8];
        *(uint4*)(sga + p * 48 + hf * 16) = v;
    }
    __syncthreads();

    float acc[2][4];
#pragma unroll
    for (int nt = 0; nt < 2; nt++)
#pragma unroll
        for (int k = 0; k < 4; k++) acc[nt][k] = 0.f;

    int m = lane & 15, kb = (lane >> 4) << 4;
    u32 base = s2u(sga);
#pragma unroll
    for (int ky = 0; ky < 3; ky++) {
#pragma unroll
        for (int kx = 0; kx < 3; kx++) {
            int tap = ky * 3 + kx;
            u32 addr = base + (u32)(((w + ky) * 18 + kx + m) * 48 + kb);
            u32 a0, a1, a2, a3;
            asm volatile(
                "ldmatrix.sync.aligned.m8n8.x4.shared.b16 {%0,%1,%2,%3}, [%4];"
                : "=r"(a0), "=r"(a1), "=r"(a2), "=r"(a3) : "r"(addr));
            const u64* wk = sW + tap * 64 + lane;
#pragma unroll
            for (int nt = 0; nt < 2; nt++) {
                u64 bv = wk[nt * 32];
                u32 bf0 = (u32)bv, bf1 = (u32)(bv >> 32);
                asm volatile(
                    "mma.sync.aligned.m16n8k16.row.col.f32.bf16.bf16.f32 "
                    "{%0,%1,%2,%3}, {%4,%5,%6,%7}, {%8,%9}, {%0,%1,%2,%3};"
                    : "+f"(acc[nt][0]), "+f"(acc[nt][1]),
                      "+f"(acc[nt][2]), "+f"(acc[nt][3])
                    : "r"(a0), "r"(a1), "r"(a2), "r"(a3), "r"(bf0), "r"(bf1));
            }
        }
    }

    int r0 = lane >> 2, t = lane & 3;
    float p0 = 0.f, p1 = 0.f;
#pragma unroll
    for (int nt = 0; nt < 2; nt++) {
        int oc = nt * 8 + 2 * t;
        float w0 = w2s[oc], w1v = w2s[oc + 1];
        float bb0 = b1s[oc], bb1 = b1s[oc + 1];
        p0 += w0 * fmaxf(acc[nt][0] + bb0, 0.f) + w1v * fmaxf(acc[nt][1] + bb1, 0.f);
        p1 += w0 * fmaxf(acc[nt][2] + bb0, 0.f) + w1v * fmaxf(acc[nt][3] + bb1, 0.f);
    }
    p0 += __shfl_xor_sync(0xffffffffu, p0, 1);
    p0 += __shfl_xor_sync(0xffffffffu, p0, 2);
    p1 += __shfl_xor_sync(0xffffffffu, p1, 1);
    p1 += __shfl_xor_sync(0xffffffffu, p1, 2);

    if (t == 0) {
        int gpx = (brow + w) * Wd + bcol + r0;
        float s0 = p0 + b2s_, s1 = p1 + b2s_;
        g_ew[b * HW + gpx] =
            frcp_ap(1.f + __expf(-s0)) * g_cons[b * HW + gpx];
        g_ew[b * HW + gpx + 8] =
            frcp_ap(1.f + __expf(-s1)) * g_cons[b * HW + gpx + 8];
    }
}

// ---------------- conv2: fp16 3x3 conv 64->64 (512 thr) + residual epilogue ----
extern "C" __global__ void __launch_bounds__(512, 2)
k_conv2(const float* __restrict__ bias,
        const float* __restrict__ xres, const float* __restrict__ alphap,
        float* __restrict__ out) {
    extern __shared__ char dsm[];
    __half* Xs = (__half*)dsm;
    u64* Ws = (u64*)(dsm + XS_BYTES);
    __shared__ float sbias[64];

    int tid = threadIdx.x;
    int lane = tid & 31, w = tid >> 5;
    int bcol = blockIdx.x * 16, brow = blockIdx.y * 8;
    int b = blockIdx.z;

    conv_stage_async(s2u(Xs), s2u(Ws),
                     g_eeb + (size_t)b * HW * 64, (const char*)(g_wq + 9216),
                     brow, bcol, tid);
    if (tid < 64) sbias[tid] = bias[tid];

    u32 acc[4][2];
#pragma unroll
    for (int nt = 0; nt < 4; nt++) { acc[nt][0] = 0u; acc[nt][1] = 0u; }

    conv_mma_core(acc, s2u(Xs), Ws, lane, w);

    int row = w & 7, ocg = w >> 3;
    int g = lane >> 2, t = lane & 3;
    float* sep = (float*)dsm;    // 64 oc x 132 px = 33.8KB, reuses Xs/Ws
    __syncthreads();
    int pl0 = row * 16 + g;
#pragma unroll
    for (int nt = 0; nt < 4; nt++) {
        int oc = ocg * 32 + nt * 8 + 2 * t;
        float2 f0 = __half22float2(*(__half2*)&acc[nt][0]);
        float2 f1 = __half22float2(*(__half2*)&acc[nt][1]);
        sep[oc * 132 + pl0]           = f0.x + sbias[oc];
        sep[(oc + 1) * 132 + pl0]     = f0.y + sbias[oc + 1];
        sep[oc * 132 + pl0 + 8]       = f1.x + sbias[oc];
        sep[(oc + 1) * 132 + pl0 + 8] = f1.y + sbias[oc + 1];
    }
    __syncthreads();
    float alpha = __ldg(alphap);
    for (int i = tid; i < 8192; i += 512) {
        int oc = i >> 7, pxl = i & 127;
        int h = brow + (pxl >> 4), col = bcol + (pxl & 15);
        int gpx = h * Wd + col;
        float v = sep[oc * 132 + pxl];
        float e = g_ew[b * HW + gpx];
        size_t oi = ((size_t)b * C + oc) * HW + gpx;
        out[oi] = xres[oi] + alpha * e * v;
    }
}

// ---------------- launch ----------------
extern "C" void kernel_launch(void* const* d_in, const int* in_sizes, int n_in,
                              void* d_out, int out_size) {
    const float* x     = (const float*)d_in[0];
    const float* ga_w1 = (const float*)d_in[3];
    const float* ga_b1 = (const float*)d_in[4];
    const float* ga_w2 = (const float*)d_in[5];
    const float* ga_b2 = (const float*)d_in[6];
    const float* cd_w1 = (const float*)d_in[7];
    const float* cd_b1 = (const float*)d_in[8];
    const float* cd_w2 = (const float*)d_in[9];
    const float* cd_b2 = (const float*)d_in[10];
    const float* ec_w1 = (const float*)d_in[11];
    const float* ec_b1 = (const float*)d_in[12];
    const float* ec_w2 = (const float*)d_in[13];
    const float* ec_b2 = (const float*)d_in[14];
    const float* alpha = (const float*)d_in[15];
    float* out = (float*)d_out;

    cudaFuncSetAttribute(k23,
                         cudaFuncAttributeMaxDynamicSharedMemorySize, K23_SMEM);
    cudaFuncSetAttribute(kmid,
                         cudaFuncAttributeMaxDynamicSharedMemorySize, CONV_SMEM);
    cudaFuncSetAttribute(k_conv2,
                         cudaFuncAttributeMaxDynamicSharedMemorySize, CONV_SMEM);

    k_pre<<<2688, 256>>>(x, ec_w1, ec_w2, ga_w1, ga_w2, cd_w1);
    k23<<<2048 + B * HW / 64, 128, K23_SMEM>>>(ga_b1, ga_b2);
    kmid<<<384, 512, CONV_SMEM>>>(ec_b1, cd_b1, cd_w2, cd_b2);
    k_conv2<<<dim3(8, 16, B), 512, CONV_SMEM>>>(ec_b2, x, alpha, out);
}

// round 16
// speedup vs baseline: 1.1107x; 1.1107x over previous
#include <cuda_runtime.h>
#include <cuda_bf16.h>
#include <math.h>

#define B 2
#define C 64
#define C4 16
#define H 128
#define Wd 128
#define HW (H * Wd)
#define EPSF 1e-6f

typedef unsigned long long u64;
typedef unsigned int u32;

// ---------------- scratch (device globals; no allocation allowed) ----------------
__device__ __align__(16) u32 g_gb[B * C * HW];               // (bf16 gx, bf16 gy) per px
__device__ float g_cons[B * HW];
__device__ float g_ew[B * HW];
__device__ __align__(16) __nv_bfloat16 g_ga2b[B * HW * C4];  // ga2, px-major bf16
__device__ __align__(16) __nv_bfloat16 g_xb[B * HW * C];     // x, NHWC bf16
__device__ __align__(16) __nv_bfloat16 g_eeb[B * HW * C];    // relu(conv1), NHWC bf16
__device__ __align__(16) u64 g_wq[2 * 9 * 4 * 64 * 4];       // conv B frags [tap][kc][pr][lane][2]
__device__ __align__(16) u64 g_wga1[2048];                   // ga layer1 B fragments
__device__ __align__(16) u64 g_wga2[256];                    // ga layer2 B fragments
__device__ __align__(16) u64 g_wcd[576];                     // cd conv B fragments

__device__ __forceinline__ u32 s2u(const void* p) {
    return (u32)__cvta_generic_to_shared(p);
}
__device__ __forceinline__ void pdl_trigger() {
    asm volatile("griddepcontrol.launch_dependents;");
}
__device__ __forceinline__ void pdl_wait() {
    asm volatile("griddepcontrol.wait;" ::: "memory");
}

// ---------------- fast math ----------------
__device__ __forceinline__ float fsqrt_ap(float v) {
    float r; asm("sqrt.approx.f32 %0, %1;" : "=f"(r) : "f"(v)); return r;
}
__device__ __forceinline__ float ftanh_ap(float v) {
    float r; asm("tanh.approx.f32 %0, %1;" : "=f"(r) : "f"(v)); return r;
}
__device__ __forceinline__ float frcp_ap(float v) {
    float r; asm("rcp.approx.f32 %0, %1;" : "=f"(r) : "f"(v)); return r;
}
__device__ __forceinline__ float fatan2_ap(float y, float x) {
    float ax = fabsf(x), ay = fabsf(y);
    float mx = fmaxf(ax, ay), mn = fminf(ax, ay);
    float z = __fdividef(mn, fmaxf(mx, 1e-30f));
    float s = z * z;
    float p = fmaf(s, -0.0117212f, 0.0526533f);
    p = fmaf(s, p, -0.1164329f);
    p = fmaf(s, p, 0.1935435f);
    p = fmaf(s, p, -0.3326235f);
    p = fmaf(s, p, 0.9999773f);
    float r = p * z;
    if (ay > ax) r = 1.57079632679f - r;
    if (x < 0.f) r = 3.14159265359f - r;
    return copysignf(r, y);
}

// ---------------- K_PRE: weight packs + g_cons zero + x->NHWC bf16 + sobel ----
__global__ __launch_bounds__(256) void k_pre(const float* __restrict__ x,
                                             const float* __restrict__ w1,
                                             const float* __restrict__ w2,
                                             const float* __restrict__ gw1,
                                             const float* __restrict__ gw2,
                                             const float* __restrict__ cw1) {
    __shared__ __align__(16) char sm[16640];
    int bx = blockIdx.x, tid = threadIdx.x;

    if (bx < 128) {
        int i = bx * 256 + tid;
        g_cons[i] = 0.f;
        if (i < 2 * 9216) {      // ec conv weights: [tap][kc][pr][lane][half]
            int cv = i / 9216;
            int r = i % 9216;
            int dlt = r / 1024;
            int r2 = r % 1024;
            int kc = r2 / 256;
            int rr = r2 % 256;
            int pr = rr >> 6;
            int rr2 = rr & 63;
            int nq = rr2 >> 1;
            int half = rr2 & 1;
            int nt = pr * 2 + half;
            int n = nt * 8 + (nq >> 2);
            int q = nq & 3;
            const float* w = cv ? w2 : w1;
            int ic0 = kc * 16 + 2 * q;
            __nv_bfloat162 lo = __floats2bfloat162_rn(
                w[(n * 64 + ic0) * 9 + dlt], w[(n * 64 + ic0 + 1) * 9 + dlt]);
            __nv_bfloat162 hi = __floats2bfloat162_rn(
                w[(n * 64 + ic0 + 8) * 9 + dlt], w[(n * 64 + ic0 + 9) * 9 + dlt]);
            g_wq[i] = (u64)(*(u32*)&lo) | ((u64)(*(u32*)&hi) << 32);
        }
        if (i < 2048) {
            int kstep = i >> 8;
            int nt = (i >> 5) & 7;
            int l = i & 31;
            int n_oc = nt * 8 + (l >> 2);
            int kn0 = kstep * 16 + (l & 3) * 2;
            int ch = kn0 >> 1;
            __nv_bfloat162 lo = __floats2bfloat162_rn(
                gw1[n_oc * 128 + ch], gw1[n_oc * 128 + 64 + ch]);
            __nv_bfloat162 hi = __floats2bfloat162_rn(
                gw1[n_oc * 128 + ch + 4], gw1[n_oc * 128 + 64 + ch + 4]);
            g_wga1[i] = (u64)(*(u32*)&lo) | ((u64)(*(u32*)&hi) << 32);
        }
        if (i < 256) {
            int kstep = i >> 6;
            int nt = (i >> 5) & 1;
            int l = i & 31;
            int n_oc = nt * 8 + (l >> 2);
            int k0 = kstep * 16 + (l & 3) * 2;
            __nv_bfloat162 lo = __floats2bfloat162_rn(
                gw2[n_oc * 64 + k0], gw2[n_oc * 64 + k0 + 1]);
            __nv_bfloat162 hi = __floats2bfloat162_rn(
                gw2[n_oc * 64 + k0 + 8], gw2[n_oc * 64 + k0 + 9]);
            g_wga2[i] = (u64)(*(u32*)&lo) | ((u64)(*(u32*)&hi) << 32);
        }
        if (i < 576) {
            int tap = i >> 6;
            int nt = (i >> 5) & 1;
            int l = i & 31;
            int n_oc = nt * 8 + (l >> 2);
            int ic0 = (l & 3) * 2;
            __nv_bfloat162 lo = __floats2bfloat162_rn(
                cw1[(n_oc * 16 + ic0) * 9 + tap],
                cw1[(n_oc * 16 + ic0 + 1) * 9 + tap]);
            __nv_bfloat162 hi = __floats2bfloat162_rn(
                cw1[(n_oc * 16 + ic0 + 8) * 9 + tap],
                cw1[(n_oc * 16 + ic0 + 9) * 9 + tap]);
            g_wcd[i] = (u64)(*(u32*)&lo) | ((u64)(*(u32*)&hi) << 32);
        }
    } else if (bx < 640) {
        int bb = bx - 128;
        int b = bb >> 8;
        int px0 = (bb & 255) * 64;
        float* s = (float*)sm;
        const float* xb = x + (size_t)b * C * HW;
        for (int i = tid; i < 4096; i += 256) {
            int ic = i >> 6, p = i & 63;
            s[p * 65 + ic] = xb[(size_t)ic * HW + px0 + p];
        }
        __syncthreads();
#pragma unroll
        for (int it = 0; it < 2; it++) {
            int idx = tid + it * 256;
            int p = idx >> 3, seg = idx & 7;
            const float* sp = &s[p * 65 + seg * 8];
            u32 u[4];
#pragma unroll
            for (int k = 0; k < 4; k++) {
                __nv_bfloat162 h2 = __floats2bfloat162_rn(sp[2 * k], sp[2 * k + 1]);
                u[k] = *(u32*)&h2;
            }
            *(uint4*)&g_xb[((size_t)b * HW + px0 + p) * 64 + seg * 8] =
                make_uint4(u[0], u[1], u[2], u[3]);
        }
    } else {
        int z = bx - 640;
        int plane = z >> 4;
        int oy = ((z >> 2) & 3) * 32, ox = (z & 3) * 32;
        float* sx = (float*)sm;
        const float* xp = x + (size_t)plane * HW;
        for (int i = tid; i < 1156; i += 256) {
            int r = i / 34, c = i - r * 34;
            int gh = oy + r - 1, gw = ox + c - 1;
            float v = 0.f;
            if ((unsigned)gh < (unsigned)H && (unsigned)gw < (unsigned)Wd)
                v = xp[gh * Wd + gw];
            sx[r * 34 + c] = v;
        }
        __syncthreads();
#pragma unroll
        for (int k = 0; k < 4; k++) {
            int px = tid + k * 256;
            int row = px >> 5, col = px & 31;
            const float* s0 = sx + row * 34 + col;
            float a00 = s0[0],  a01 = s0[1],  a02 = s0[2];
            float a10 = s0[34],               a12 = s0[36];
            float a20 = s0[68], a21 = s0[69], a22 = s0[70];
            float gx = (a02 - a00) + 2.f * (a12 - a10) + (a22 - a20);
            float gy = (a20 - a00) + 2.f * (a21 - a01) + (a22 - a02);
            __nv_bfloat162 hv = __floats2bfloat162_rn(gx, gy);
            g_gb[plane * HW + (oy + row) * Wd + ox + col] = *(u32*)&hv;
        }
    }
}

// ---------------- K23: merged k3 (consistency) + k2 (1x1 mma chain) -----------
#define K23_SMEM 43328
extern "C" __global__ void __launch_bounds__(128)
k23(const float* __restrict__ b1, const float* __restrict__ b2) {
    extern __shared__ char dsm[];
    int tid = threadIdx.x;
    int bi = blockIdx.x;
    pdl_trigger();   // let kmid (conv1 half: k_pre-only deps) launch early

    if (bi < 2048) {
        int b = bi >> 10;
        int rem = bi & 1023;
        int c = rem >> 4;
        int tile = rem & 15;
        int oy = (tile >> 2) * 32, ox = (tile & 3) * 32;
        float* sm0 = (float*)dsm;
        float* sm1 = sm0 + 1296;
        float* sm2 = sm1 + 1296;
        float* h0 = sm2 + 1296;
        float* h1 = h0 + 1152;
        float* h2 = h1 + 1152;

        const u32* gb = g_gb + (size_t)(b * C + c) * HW;
        for (int i = tid; i < 1296; i += 128) {
            int r = i / 36, k = i - r * 36;
            int gh = oy + r - 2, gw = ox + k - 2;
            float m0 = 0.f, m1 = 0.f, m2 = 0.f;
            if ((unsigned)gh < (unsigned)H && (unsigned)gw < (unsigned)Wd) {
                u32 v = gb[gh * Wd + gw];
                float2 g = __bfloat1622float2(*(__nv_bfloat162*)&v);
                float gx = g.x, gy = g.y;
                float mag = fsqrt_ap(gx * gx + gy * gy + EPSF);
                float dir = fatan2_ap(gy, gx);
                m0 = mag;
                m1 = mag * dir;
                m2 = m1 * dir;
            }
            sm0[i] = m0;
            sm1[i] = m1;
            sm2[i] = m2;
        }
        __syncthreads();
        for (int i = tid; i < 1152; i += 128) {
            int r = i >> 5, k = i & 31;
            const float* p0 = sm0 + r * 36 + k;
            const float* p1 = sm1 + r * 36 + k;
            const float* p2 = sm2 + r * 36 + k;
            float a0 = 0.f, a1 = 0.f, a2 = 0.f;
#pragma unroll
            for (int d = 0; d < 5; d++) {
                a0 += p0[d];
                a1 += p1[d];
                a2 += p2[d];
            }
            h0[i] = a0;
            h1[i] = a1;
            h2[i] = a2;
        }
        __syncthreads();
        int ty = tid >> 5, tx = tid & 31;
#pragma unroll
        for (int j = 0; j < 8; j++) {
            int row = j * 4 + ty;
            float s0 = 0.f, s1 = 0.f, s2 = 0.f;
#pragma unroll
            for (int d = 0; d < 5; d++) {
                s0 += h0[(row + d) * 32 + tx];
                s1 += h1[(row + d) * 32 + tx];
                s2 += h2[(row + d) * 32 + tx];
            }
            float inv = frcp_ap(s0 + EPSF);
            float wmean = s1 * inv;
            float wvar = (s2 - 2.f * wmean * s1 + wmean * wmean * s0) * inv;
            wvar = fmaxf(wvar, 0.f);
            float cv = (1.f - ftanh_ap(fsqrt_ap(wvar))) * (1.f / (float)C);
            atomicAdd(&g_cons[b * HW + (oy + row) * Wd + (ox + tx)], cv);
        }
        return;
    }

    __nv_bfloat16* sIn = (__nv_bfloat16*)dsm;
    __nv_bfloat16* sHid = (__nv_bfloat16*)(dsm + 16384);
    u64* sW1 = (u64*)(dsm + 24576);
    u64* sW2 = (u64*)(dsm + 40960);
    float* sb1 = (float*)(dsm + 43008);
    float* sb2 = (float*)(dsm + 43264);

    int lane = tid & 31, w = tid >> 5;
    int bk = bi - 2048;
    int b = bk >> 8;
    int px0 = (bk & 255) * 64;

    {
        const float4* s1 = (const float4*)g_wga1;
        float4* d1 = (float4*)sW1;
#pragma unroll
        for (int i = tid; i < 1024; i += 128) d1[i] = s1[i];
        ((float4*)sW2)[tid] = ((const float4*)g_wga2)[tid];
        if (tid < 64) sb1[tid] = b1[tid];
        if (tid < 16) sb2[tid] = b2[tid];
    }
    const u32* gbb = g_gb + (size_t)b * C * HW + px0;
    for (int i = tid; i < 4096; i += 128) {
        int cp = i >> 6, px = i & 63;
        u32 v = gbb[(size_t)cp * HW + px];
        int half = cp >> 5, c4 = (cp & 31) * 4;
        *(u32*)(dsm + half * 8192 + px * 128 +
                ((u32)c4 ^ ((u32)(px & 7) << 4))) = v;
    }
    __syncthreads();

    int m = lane & 15, kb = (lane >> 4) << 4;
    int p = w * 16 + m;
    u32 swz = (u32)((p & 7) << 4);
    u32 arow = s2u(sIn) + p * 128;

    float acc[8][4];
#pragma unroll
    for (int nt = 0; nt < 8; nt++)
#pragma unroll
        for (int k = 0; k < 4; k++) acc[nt][k] = 0.f;

#pragma unroll
    for (int kc = 0; kc < 8; kc++) {
        u32 a0, a1, a2, a3;
        u32 addr = arow + (kc >> 2) * 8192 + (((u32)((kc & 3) * 32 + kb)) ^ swz);
        asm volatile(
            "ldmatrix.sync.aligned.m8n8.x4.shared.b16 {%0,%1,%2,%3}, [%4];"
            : "=r"(a0), "=r"(a1), "=r"(a2), "=r"(a3) : "r"(addr));
        const u64* wk = sW1 + (size_t)kc * 256 + lane;
#pragma unroll
        for (int nt = 0; nt < 8; nt++) {
            u64 bv = wk[nt * 32];
            u32 bf0 = (u32)bv, bf1 = (u32)(bv >> 32);
            asm volatile(
                "mma.sync.aligned.m16n8k16.row.col.f32.bf16.bf16.f32 "
                "{%0,%1,%2,%3}, {%4,%5,%6,%7}, {%8,%9}, {%0,%1,%2,%3};"
                : "+f"(acc[nt][0]), "+f"(acc[nt][1]),
                  "+f"(acc[nt][2]), "+f"(acc[nt][3])
                : "r"(a0), "r"(a1), "r"(a2), "r"(a3), "r"(bf0), "r"(bf1));
        }
    }

    int rr = lane >> 2, cc0 = (lane & 3) * 2;
    int pr0 = w * 16 + rr, pr1 = pr0 + 8;
#pragma unroll
    for (int nt = 0; nt < 8; nt++) {
        int oc = nt * 8 + cc0;
        float bb0 = sb1[oc], bb1 = sb1[oc + 1];
        __nv_bfloat162 v01 = __floats2bfloat162_rn(
            fmaxf(acc[nt][0] + bb0, 0.f), fmaxf(acc[nt][1] + bb1, 0.f));
        __nv_bfloat162 v23 = __floats2bfloat162_rn(
            fmaxf(acc[nt][2] + bb0, 0.f), fmaxf(acc[nt][3] + bb1, 0.f));
        *(u32*)((char*)sHid + pr0 * 128 +
                ((u32)(oc * 2) ^ ((u32)(pr0 & 7) << 4))) = *(u32*)&v01;
        *(u32*)((char*)sHid + pr1 * 128 +
                ((u32)(oc * 2) ^ ((u32)(pr1 & 7) << 4))) = *(u32*)&v23;
    }
    __syncwarp();

    float a2c[2][4];
#pragma unroll
    for (int nt = 0; nt < 2; nt++)
#pragma unroll
        for (int k = 0; k < 4; k++) a2c[nt][k] = 0.f;

    u32 hrow = s2u(sHid) + p * 128;
#pragma unroll
    for (int kc = 0; kc < 4; kc++) {
        u32 a0, a1, a2, a3;
        u32 addr = hrow + (((u32)(kc * 32 + kb)) ^ swz);
        asm volatile(
            "ldmatrix.sync.aligned.m8n8.x4.shared.b16 {%0,%1,%2,%3}, [%4];"
            : "=r"(a0), "=r"(a1), "=r"(a2), "=r"(a3) : "r"(addr));
        const u64* wk = sW2 + (size_t)kc * 64 + lane;
#pragma unroll
        for (int nt = 0; nt < 2; nt++) {
            u64 bv = wk[nt * 32];
            u32 bf0 = (u32)bv, bf1 = (u32)(bv >> 32);
            asm volatile(
                "mma.sync.aligned.m16n8k16.row.col.f32.bf16.bf16.f32 "
                "{%0,%1,%2,%3}, {%4,%5,%6,%7}, {%8,%9}, {%0,%1,%2,%3};"
                : "+f"(a2c[nt][0]), "+f"(a2c[nt][1]),
                  "+f"(a2c[nt][2]), "+f"(a2c[nt][3])
                : "r"(a0), "r"(a1), "r"(a2), "r"(a3), "r"(bf0), "r"(bf1));
        }
    }

    size_t pxg0 = (size_t)b * HW + px0 + w * 16 + rr;
#pragma unroll
    for (int nt = 0; nt < 2; nt++) {
        int oc = nt * 8 + cc0;
        float bb0 = sb2[oc], bb1 = sb2[oc + 1];
        __nv_bfloat162 v01 = __floats2bfloat162_rn(
            fmaxf(a2c[nt][0] + bb0, 0.f), fmaxf(a2c[nt][1] + bb1, 0.f));
        __nv_bfloat162 v23 = __floats2bfloat162_rn(
            fmaxf(a2c[nt][2] + bb0, 0.f), fmaxf(a2c[nt][3] + bb1, 0.f));
        *(u32*)&g_ga2b[pxg0 * 16 + oc] = *(u32*)&v01;
        *(u32*)&g_ga2b[(pxg0 + 8) * 16 + oc] = *(u32*)&v23;
    }
}

// ---------------- conv config: 64-oc blocks, cp.async everything ---------------
#define XS_BYTES 23040
#define WS_BYTES 73728
#define CONV_SMEM (XS_BYTES + WS_BYTES)

// R12 staging: Xs + ky0 weights group0; ky1, ky2 groups 1,2
__device__ __forceinline__ void conv_stage_async(u32 xs_s, u32 ws_s,
                                                 const __nv_bfloat16* xb,
                                                 const char* wsrc,
                                                 int brow, int bcol, int tid) {
    for (int i = tid; i < 1440; i += 256) {
        int p = i >> 3, seg = i & 7;
        int r = p / 18, c = p - r * 18;
        int gh = brow - 1 + r, gc = bcol - 1 + c;
        bool ok = (unsigned)gh < (unsigned)H && (unsigned)gc < (unsigned)Wd;
        const char* src = (const char*)xb +
                          (ok ? ((size_t)(gh * Wd + gc)) * 128 + seg * 16 : 0);
        int sz = ok ? 16 : 0;
        u32 dst = xs_s + (u32)(p * 128 + ((seg * 16) ^ ((p & 7) << 4)));
        asm volatile("cp.async.ca.shared.global [%0], [%1], 16, %2;"
                     :: "r"(dst), "l"(src), "r"(sz) : "memory");
    }
#pragma unroll
    for (int j = 0; j < 6; j++) {
        int i = j * 256 + tid;
        asm volatile("cp.async.ca.shared.global [%0], [%1], 16;"
                     :: "r"(ws_s + i * 16), "l"(wsrc + (size_t)i * 16) : "memory");
    }
    asm volatile("cp.async.commit_group;" ::: "memory");
#pragma unroll
    for (int g3 = 1; g3 < 3; g3++) {
#pragma unroll
        for (int j = 0; j < 6; j++) {
            int i = g3 * 1536 + j * 256 + tid;
            asm volatile("cp.async.ca.shared.global [%0], [%1], 16;"
                         :: "r"(ws_s + i * 16), "l"(wsrc + (size_t)i * 16)
                         : "memory");
        }
        asm volatile("cp.async.commit_group;" ::: "memory");
    }
}

// R12 core: f32-acc bf16 mma, incremental waits (used by conv1)
__device__ __forceinline__ void conv_mma_core(float acc[8][4], u32 xs_base,
                                              const u64* Ws, int lane, int w) {
    int m = lane & 15;
    int kb = (lane >> 4) << 4;
#pragma unroll
    for (int ky = 0; ky < 3; ky++) {
        if (ky == 0) asm volatile("cp.async.wait_group 2;" ::: "memory");
        else if (ky == 1) asm volatile("cp.async.wait_group 1;" ::: "memory");
        else asm volatile("cp.async.wait_group 0;" ::: "memory");
        __syncthreads();
#pragma unroll
        for (int kx = 0; kx < 3; kx++) {
            int p = (w + ky) * 18 + kx + m;
            u32 arow = xs_base + p * 128;
            u32 swz = (u32)((p & 7) << 4);
            const u64* wtap = Ws + (ky * 3 + kx) * 1024 + lane * 2;
#pragma unroll
            for (int kc = 0; kc < 4; kc++) {
                u32 a0, a1, a2, a3;
                u32 addr = arow + ((u32)(kc * 32 + kb) ^ swz);
                asm volatile(
                    "ldmatrix.sync.aligned.m8n8.x4.shared.b16 "
                    "{%0,%1,%2,%3}, [%4];"
                    : "=r"(a0), "=r"(a1), "=r"(a2), "=r"(a3)
                    : "r"(addr));
                const u64* wk = wtap + kc * 256;
#pragma unroll
                for (int pr = 0; pr < 4; pr++) {
                    ulonglong2 bv2 = *(const ulonglong2*)(wk + pr * 64);
                    u32 b0 = (u32)bv2.x, b1 = (u32)(bv2.x >> 32);
                    asm volatile(
                        "mma.sync.aligned.m16n8k16.row.col.f32.bf16.bf16.f32 "
                        "{%0,%1,%2,%3}, {%4,%5,%6,%7}, {%8,%9}, {%0,%1,%2,%3};"
                        : "+f"(acc[2 * pr][0]), "+f"(acc[2 * pr][1]),
                          "+f"(acc[2 * pr][2]), "+f"(acc[2 * pr][3])
                        : "r"(a0), "r"(a1), "r"(a2), "r"(a3),
                          "r"(b0), "r"(b1));
                    u32 b2 = (u32)bv2.y, b3 = (u32)(bv2.y >> 32);
                    asm volatile(
                        "mma.sync.aligned.m16n8k16.row.col.f32.bf16.bf16.f32 "
                        "{%0,%1,%2,%3}, {%4,%5,%6,%7}, {%8,%9}, {%0,%1,%2,%3};"
                        : "+f"(acc[2 * pr + 1][0]), "+f"(acc[2 * pr + 1][1]),
                          "+f"(acc[2 * pr + 1][2]), "+f"(acc[2 * pr + 1][3])
                        : "r"(a0), "r"(a1), "r"(a2), "r"(a3),
                          "r"(b2), "r"(b3));
                }
            }
        }
    }
}

// ---------------- KMID: merged conv1 (64-oc) + k4 (cd branch), PDL ------------
extern "C" __global__ void __launch_bounds__(256)
kmid(const float* __restrict__ ecb1,
     const float* __restrict__ cb1, const float* __restrict__ cw2,
     const float* __restrict__ cb2) {
    extern __shared__ char dsm[];
    __shared__ float sbias[64];
    int tid = threadIdx.x;
    int lane = tid & 31, w = tid >> 5;
    int bi = blockIdx.x;
    pdl_trigger();   // let conv2 launch early (its pre-wait reads only k_pre data)

    if (bi < 256) {
        // conv1 half: depends only on k_pre outputs (g_xb, g_wq) — no pdl_wait.
        __nv_bfloat16* Xs = (__nv_bfloat16*)dsm;
        u64* Ws = (u64*)(dsm + XS_BYTES);
        int b = bi >> 7;
        int rem = bi & 127;
        int brow = (rem >> 3) * 8, bcol = (rem & 7) * 16;

        conv_stage_async(s2u(Xs), s2u(Ws),
                         g_xb + (size_t)b * HW * 64, (const char*)g_wq,
                         brow, bcol, tid);
        if (tid < 64) sbias[tid] = ecb1[tid];

        float acc[8][4];
#pragma unroll
        for (int nt = 0; nt < 8; nt++)
#pragma unroll
            for (int k = 0; k < 4; k++) acc[nt][k] = 0.f;

        conv_mma_core(acc, s2u(Xs), Ws, lane, w);

        int g = lane >> 2, t = lane & 3;
        int h = brow + w;
        size_t px0 = (size_t)b * HW + h * Wd + bcol + g;
#pragma unroll
        for (int nt = 0; nt < 8; nt++) {
            int oc = nt * 8 + 2 * t;
            float b0f = sbias[oc], b1f = sbias[oc + 1];
            __nv_bfloat162 p01 = __floats2bfloat162_rn(
                fmaxf(acc[nt][0] + b0f, 0.f), fmaxf(acc[nt][1] + b1f, 0.f));
            __nv_bfloat162 p23 = __floats2bfloat162_rn(
                fmaxf(acc[nt][2] + b0f, 0.f), fmaxf(acc[nt][3] + b1f, 0.f));
            *(u32*)&g_eeb[px0 * 64 + oc] = *(u32*)&p01;
            *(u32*)&g_eeb[(px0 + 8) * 64 + oc] = *(u32*)&p23;
        }
        return;
    }

    // ---- k4: cd branch — reads k23 outputs, must wait ----
    char* sga = dsm;
    u64* sW = (u64*)(dsm + 8640);
    __shared__ float b1s[16], w2s[16];
    __shared__ float b2s_;

    int bk = bi - 256;
    int b = bk >> 7;
    int t8 = bk & 127;
    int brow = (t8 >> 3) * 8, bcol = (t8 & 7) * 16;

    for (int i = tid; i < 576; i += 256) sW[i] = g_wcd[i];   // k_pre data
    if (tid < 16) { b1s[tid] = cb1[tid]; w2s[tid] = cw2[tid]; }
    if (tid == 0) b2s_ = cb2[0];

    pdl_wait();   // k23 (g_ga2b, g_cons) must be complete from here on

    const __nv_bfloat16* gb = g_ga2b + (size_t)b * HW * 16;
    for (int i = tid; i < 360; i += 256) {
        int p = i >> 1, hf = i & 1;
        int r = p / 18, c = p - r * 18;
        int gh = brow - 1 + r, gc = bcol - 1 + c;
        uint4 v = make_uint4(0, 0, 0, 0);
        if ((unsigned)gh < (unsigned)H && (unsigned)gc < (unsigned)Wd)
            v = *(const uint4*)&gb[(size_t)(gh * Wd + gc) * 16 + hf * 8];
        *(uint4*)(sga + p * 48 + hf * 16) = v;
    }
    __syncthreads();

    float acc[2][4];
#pragma unroll
    for (int nt = 0; nt < 2; nt++)
#pragma unroll
        for (int k = 0; k < 4; k++) acc[nt][k] = 0.f;

    int m = lane & 15, kb = (lane >> 4) << 4;
    u32 base = s2u(sga);
#pragma unroll
    for (int ky = 0; ky < 3; ky++) {
#pragma unroll
        for (int kx = 0; kx < 3; kx++) {
            int tap = ky * 3 + kx;
            u32 addr = base + (u32)(((w + ky) * 18 + kx + m) * 48 + kb);
            u32 a0, a1, a2, a3;
            asm volatile(
                "ldmatrix.sync.aligned.m8n8.x4.shared.b16 {%0,%1,%2,%3}, [%4];"
                : "=r"(a0), "=r"(a1), "=r"(a2), "=r"(a3) : "r"(addr));
            const u64* wk = sW + tap * 64 + lane;
#pragma unroll
            for (int nt = 0; nt < 2; nt++) {
                u64 bv = wk[nt * 32];
                u32 bf0 = (u32)bv, bf1 = (u32)(bv >> 32);
                asm volatile(
                    "mma.sync.aligned.m16n8k16.row.col.f32.bf16.bf16.f32 "
                    "{%0,%1,%2,%3}, {%4,%5,%6,%7}, {%8,%9}, {%0,%1,%2,%3};"
                    : "+f"(acc[nt][0]), "+f"(acc[nt][1]),
                      "+f"(acc[nt][2]), "+f"(acc[nt][3])
                    : "r"(a0), "r"(a1), "r"(a2), "r"(a3), "r"(bf0), "r"(bf1));
            }
        }
    }

    int r0 = lane >> 2, t = lane & 3;
    float p0 = 0.f, p1 = 0.f;
#pragma unroll
    for (int nt = 0; nt < 2; nt++) {
        int oc = nt * 8 + 2 * t;
        float w0 = w2s[oc], w1v = w2s[oc + 1];
        float bb0 = b1s[oc], bb1 = b1s[oc + 1];
        p0 += w0 * fmaxf(acc[nt][0] + bb0, 0.f) + w1v * fmaxf(acc[nt][1] + bb1, 0.f);
        p1 += w0 * fmaxf(acc[nt][2] + bb0, 0.f) + w1v * fmaxf(acc[nt][3] + bb1, 0.f);
    }
    p0 += __shfl_xor_sync(0xffffffffu, p0, 1);
    p0 += __shfl_xor_sync(0xffffffffu, p0, 2);
    p1 += __shfl_xor_sync(0xffffffffu, p1, 1);
    p1 += __shfl_xor_sync(0xffffffffu, p1, 2);

    if (t == 0) {
        int gpx = (brow + w) * Wd + bcol + r0;
        float s0 = p0 + b2s_, s1 = p1 + b2s_;
        g_ew[b * HW + gpx] =
            frcp_ap(1.f + __expf(-s0)) * g_cons[b * HW + gpx];
        g_ew[b * HW + gpx + 8] =
            frcp_ap(1.f + __expf(-s1)) * g_cons[b * HW + gpx + 8];
    }
}

// ---------------- conv2: PDL — prefetch weights, wait, then Xs + compute -------
extern "C" __global__ void __launch_bounds__(256, 2)
k_conv2(const float* __restrict__ bias,
        const float* __restrict__ xres, const float* __restrict__ alphap,
        float* __restrict__ out) {
    extern __shared__ char dsm[];
    __nv_bfloat16* Xs = (__nv_bfloat16*)dsm;
    u64* Ws = (u64*)(dsm + XS_BYTES);
    __shared__ float sbias[64];

    int tid = threadIdx.x;
    int lane = tid & 31, w = tid >> 5;
    int bcol = blockIdx.x * 16, brow = blockIdx.y * 8;
    int b = blockIdx.z;

    // pre-wait: stage ALL weights (k_pre data) — overlaps kmid execution
    {
        u32 ws_s = s2u(Ws);
        const char* wsrc = (const char*)(g_wq + 9216);
#pragma unroll
        for (int g3 = 0; g3 < 3; g3++) {
#pragma unroll
            for (int j = 0; j < 6; j++) {
                int i = g3 * 1536 + j * 256 + tid;
                asm volatile("cp.async.ca.shared.global [%0], [%1], 16;"
                             :: "r"(ws_s + i * 16), "l"(wsrc + (size_t)i * 16)
                             : "memory");
            }
        }
        asm volatile("cp.async.commit_group;" ::: "memory");
    }
    if (tid < 64) sbias[tid] = bias[tid];

    pdl_wait();   // kmid (g_eeb, g_ew) must be complete from here on

    // Xs staging (group 1)
    {
        const __nv_bfloat16* xb = g_eeb + (size_t)b * HW * 64;
        u32 xs_s = s2u(Xs);
        for (int i = tid; i < 1440; i += 256) {
            int p = i >> 3, seg = i & 7;
            int r = p / 18, c = p - r * 18;
            int gh = brow - 1 + r, gc = bcol - 1 + c;
            bool ok = (unsigned)gh < (unsigned)H && (unsigned)gc < (unsigned)Wd;
            const char* src = (const char*)xb +
                              (ok ? ((size_t)(gh * Wd + gc)) * 128 + seg * 16 : 0);
            int sz = ok ? 16 : 0;
            u32 dst = xs_s + (u32)(p * 128 + ((seg * 16) ^ ((p & 7) << 4)));
            asm volatile("cp.async.ca.shared.global [%0], [%1], 16, %2;"
                         :: "r"(dst), "l"(src), "r"(sz) : "memory");
        }
        asm volatile("cp.async.commit_group;" ::: "memory");
    }
    asm volatile("cp.async.wait_group 0;" ::: "memory");
    __syncthreads();

    float acc[8][4];
#pragma unroll
    for (int nt = 0; nt < 8; nt++)
#pragma unroll
        for (int k = 0; k < 4; k++) acc[nt][k] = 0.f;

    u32 xs_base = s2u(Xs);
    int m = lane & 15;
    int kb = (lane >> 4) << 4;

    // compute: all data resident, no intra-loop waits/barriers
#pragma unroll
    for (int ky = 0; ky < 3; ky++) {
#pragma unroll
        for (int kx = 0; kx < 3; kx++) {
            int p = (w + ky) * 18 + kx + m;
            u32 arow = xs_base + p * 128;
            u32 swz = (u32)((p & 7) << 4);
            const u64* wtap = Ws + (ky * 3 + kx) * 1024 + lane * 2;
#pragma unroll
            for (int kc = 0; kc < 4; kc++) {
                u32 a0, a1, a2, a3;
                u32 addr = arow + ((u32)(kc * 32 + kb) ^ swz);
                asm volatile(
                    "ldmatrix.sync.aligned.m8n8.x4.shared.b16 "
                    "{%0,%1,%2,%3}, [%4];"
                    : "=r"(a0), "=r"(a1), "=r"(a2), "=r"(a3)
                    : "r"(addr));
                const u64* wk = wtap + kc * 256;
#pragma unroll
                for (int pr = 0; pr < 4; pr++) {
                    ulonglong2 bv2 = *(const ulonglong2*)(wk + pr * 64);
                    u32 b0 = (u32)bv2.x, b1 = (u32)(bv2.x >> 32);
                    asm volatile(
                        "mma.sync.aligned.m16n8k16.row.col.f32.bf16.bf16.f32 "
                        "{%0,%1,%2,%3}, {%4,%5,%6,%7}, {%8,%9}, {%0,%1,%2,%3};"
                        : "+f"(acc[2 * pr][0]), "+f"(acc[2 * pr][1]),
                          "+f"(acc[2 * pr][2]), "+f"(acc[2 * pr][3])
                        : "r"(a0), "r"(a1), "r"(a2), "r"(a3),
                          "r"(b0), "r"(b1));
                    u32 b2 = (u32)bv2.y, b3 = (u32)(bv2.y >> 32);
                    asm volatile(
                        "mma.sync.aligned.m16n8k16.row.col.f32.bf16.bf16.f32 "
                        "{%0,%1,%2,%3}, {%4,%5,%6,%7}, {%8,%9}, {%0,%1,%2,%3};"
                        : "+f"(acc[2 * pr + 1][0]), "+f"(acc[2 * pr + 1][1]),
                          "+f"(acc[2 * pr + 1][2]), "+f"(acc[2 * pr + 1][3])
                        : "r"(a0), "r"(a1), "r"(a2), "r"(a3),
                          "r"(b2), "r"(b3));
                }
            }
        }
    }

    int g = lane >> 2, t = lane & 3;
    float* sep = (float*)dsm;
    __syncthreads();
    int pl0 = w * 16 + g;
#pragma unroll
    for (int nt = 0; nt < 8; nt++) {
        int oc = nt * 8 + 2 * t;
        sep[oc * 132 + pl0]           = acc[nt][0] + sbias[oc];
        sep[(oc + 1) * 132 + pl0]     = acc[nt][1] + sbias[oc + 1];
        sep[oc * 132 + pl0 + 8]       = acc[nt][2] + sbias[oc];
        sep[(oc + 1) * 132 + pl0 + 8] = acc[nt][3] + sbias[oc + 1];
    }
    __syncthreads();
    float alpha = __ldg(alphap);
    for (int i = tid; i < 8192; i += 256) {
        int oc = i >> 7, pxl = i & 127;
        int h = brow + (pxl >> 4), col = bcol + (pxl & 15);
        int gpx = h * Wd + col;
        float v = sep[oc * 132 + pxl];
        float e = g_ew[b * HW + gpx];
        size_t oi = ((size_t)b * C + oc) * HW + gpx;
        out[oi] = xres[oi] + alpha * e * v;
    }
}

// ---------------- launch ----------------
extern "C" void kernel_launch(void* const* d_in, const int* in_sizes, int n_in,
                              void* d_out, int out_size) {
    const float* x     = (const float*)d_in[0];
    const float* ga_w1 = (const float*)d_in[3];
    const float* ga_b1 = (const float*)d_in[4];
    const float* ga_w2 = (const float*)d_in[5];
    const float* ga_b2 = (const float*)d_in[6];
    const float* cd_w1 = (const float*)d_in[7];
    const float* cd_b1 = (const float*)d_in[8];
    const float* cd_w2 = (const float*)d_in[9];
    const float* cd_b2 = (const float*)d_in[10];
    const float* ec_w1 = (const float*)d_in[11];
    const float* ec_b1 = (const float*)d_in[12];
    const float* ec_w2 = (const float*)d_in[13];
    const float* ec_b2 = (const float*)d_in[14];
    const float* alpha = (const float*)d_in[15];
    float* out = (float*)d_out;

    cudaFuncSetAttribute(k23,
                         cudaFuncAttributeMaxDynamicSharedMemorySize, K23_SMEM);
    cudaFuncSetAttribute(kmid,
                         cudaFuncAttributeMaxDynamicSharedMemorySize, CONV_SMEM);
    cudaFuncSetAttribute(k_conv2,
                         cudaFuncAttributeMaxDynamicSharedMemorySize, CONV_SMEM);

    k_pre<<<2688, 256>>>(x, ec_w1, ec_w2, ga_w1, ga_w2, cd_w1);
    k23<<<2048 + B * HW / 64, 128, K23_SMEM>>>(ga_b1, ga_b2);

    cudaLaunchAttribute attr[1];
    attr[0].id = cudaLaunchAttributeProgrammaticStreamSerialization;
    attr[0].val.programmaticStreamSerializationAllowed = 1;

    {
        cudaLaunchConfig_t cfg = {};
        cfg.gridDim = dim3(512, 1, 1);
        cfg.blockDim = dim3(256, 1, 1);
        cfg.dynamicSmemBytes = CONV_SMEM;
        cfg.attrs = attr;
        cfg.numAttrs = 1;
        cudaLaunchKernelEx(&cfg, kmid, ec_b1, cd_b1, cd_w2, cd_b2);
    }
    {
        cudaLaunchConfig_t cfg = {};
        cfg.gridDim = dim3(8, 16, B);
        cfg.blockDim = dim3(256, 1, 1);
        cfg.dynamicSmemBytes = CONV_SMEM;
        cfg.attrs = attr;
        cfg.numAttrs = 1;
        cudaLaunchKernelEx(&cfg, k_conv2, ec_b2, x, alpha, out);
    }
}